// round 8
// baseline (speedup 1.0000x reference)
#include <cuda_runtime.h>

// Encoding layer on tensor cores (tf32 mma.sync), B=16, D=128, N=4096, K=32.
// One CTA = one (b, chunk) tile of 256 n (two inner 128-n tiles). asum*C folded
// into the per-chunk epilogue. Cross-chunk reduction fused: per-batch spin
// barrier, then ALL 16 CTAs of the batch reduce disjoint output slices in a
// fixed order (bitwise deterministic). Counters self-reset for graph replay.

#define Dd   128
#define Kk   32
#define Bb   16
#define HWn  4096
#define TN   256
#define TIN  128
#define NT   2
#define CH   16          // chunks per batch
#define NTH  256
#define ST   132

#define XS_OFF   0                    // [128][ST]
#define CS_OFF   (128*ST)             // [32][ST]
#define AS_OFF   (160*ST)             // [32][ST]
#define X2P_OFF  (192*ST)             // [8][128]
#define X2S_OFF  (X2P_OFF + 1024)     // [128]
#define C2S_OFF  (X2S_OFF + 128)      // [32]
#define RED_OFF  (C2S_OFF + 32)       // [256]
#define ASUM_OFF (RED_OFF + 256)      // [32]
#define SM_FLOATS (ASUM_OFF + 32)
#define SM_BYTES  (SM_FLOATS * 4)

__device__ float g_scratchE[Bb*CH*Kk*Dd];   // 4 MB partial E (asum*C folded)
__device__ int   g_cnt[Bb];                 // arrival counter (zero-init)
__device__ int   g_cnt2[Bb];                // completion counter (zero-init)

__device__ __forceinline__ unsigned f2tf(float f) {
    unsigned r; asm("cvt.rna.tf32.f32 %0, %1;" : "=r"(r) : "f"(f)); return r;
}
__device__ __forceinline__ void mma_tf32(float* d,
    unsigned a0, unsigned a1, unsigned a2, unsigned a3, unsigned b0, unsigned b1) {
    asm("mma.sync.aligned.m16n8k8.row.col.f32.tf32.tf32.f32 "
        "{%0,%1,%2,%3}, {%4,%5,%6,%7}, {%8,%9}, {%0,%1,%2,%3};"
        : "+f"(d[0]), "+f"(d[1]), "+f"(d[2]), "+f"(d[3])
        : "r"(a0), "r"(a1), "r"(a2), "r"(a3), "r"(b0), "r"(b1));
}
__device__ __forceinline__ unsigned fbits(float f) { return __float_as_uint(f); }

__global__ void __launch_bounds__(NTH, 2) enc_main(
    const float* __restrict__ x,      // (B, D, HWn)
    const float* __restrict__ cw,     // (K, D)
    const float* __restrict__ scale,  // (K,)
    float* __restrict__ out)          // (B, K, D)
{
    extern __shared__ float sm[];
    const int tid = threadIdx.x;
    const int w   = tid >> 5;
    const int l   = tid & 31;
    const int lr  = l >> 2;
    const int lc  = l & 3;
    const int b     = blockIdx.y;
    const int chunk = blockIdx.x;
    const float* xb = x + (size_t)b * Dd * HWn + chunk * TN;

    // ---- stage Cs (tf32-rounded) ----
    #pragma unroll 1
    for (int i = tid; i < Kk*Dd; i += NTH)
        sm[CS_OFF + (i >> 7)*ST + (i & 127)] = __uint_as_float(f2tf(cw[i]));
    __syncthreads();
    {
        int k = tid >> 3, s8 = tid & 7;
        float part = 0.f;
        #pragma unroll
        for (int j = 0; j < 16; j++) {
            float c = sm[CS_OFF + k*ST + s8*16 + j];
            part += c*c;
        }
        sm[RED_OFF + tid] = part;
    }
    __syncthreads();
    if (tid < Kk) {
        float s = 0.f;
        #pragma unroll
        for (int j = 0; j < 8; j++) s += sm[RED_OFF + tid*8 + j];
        sm[C2S_OFF + tid] = s;
    }
    __syncthreads();

    float c2v[4][2], scv[4][2];
    #pragma unroll
    for (int kt = 0; kt < 4; kt++)
        #pragma unroll
        for (int j = 0; j < 2; j++) {
            int k = 8*kt + 2*lc + j;
            c2v[kt][j] = sm[C2S_OFF + k];
            scv[kt][j] = scale[k];
        }

    const int rowA  = 16*w + lr;
    const int dwarp = 16*w;

    float D2[2][2][4];
    #pragma unroll
    for (int mt = 0; mt < 2; mt++)
        #pragma unroll
        for (int nt = 0; nt < 2; nt++)
            #pragma unroll
            for (int r = 0; r < 4; r++) D2[mt][nt][r] = 0.f;
    float asum_acc = 0.f;            // valid in tid<32

    for (int t = 0; t < NT; t++) {
        __syncthreads();

        // ---- fill Xs (tf32) + exact-fp32 x2 partials ----
        {
            const int nl = tid & 31, dq = tid >> 5;
            #pragma unroll
            for (int p = 0; p < 4; p++) {
                const int n = p*32 + nl;
                const float* src = xb + (size_t)(dq*16)*HWn + t*TIN + n;
                float* dst = &sm[XS_OFF + n*ST + dq*16];
                float part = 0.f;
                #pragma unroll
                for (int j = 0; j < 4; j++) {
                    float v0 = src[(size_t)(4*j+0)*HWn];
                    float v1 = src[(size_t)(4*j+1)*HWn];
                    float v2 = src[(size_t)(4*j+2)*HWn];
                    float v3 = src[(size_t)(4*j+3)*HWn];
                    part += v0*v0 + v1*v1 + v2*v2 + v3*v3;
                    float4 o;
                    o.x = __uint_as_float(f2tf(v0)); o.y = __uint_as_float(f2tf(v1));
                    o.z = __uint_as_float(f2tf(v2)); o.w = __uint_as_float(f2tf(v3));
                    *(float4*)(dst + 4*j) = o;
                }
                sm[X2P_OFF + dq*128 + n] = part;
            }
        }
        __syncthreads();

        if (tid < 128) {
            float s = 0.f;
            #pragma unroll
            for (int dq = 0; dq < 8; dq++) s += sm[X2P_OFF + dq*128 + tid];
            sm[X2S_OFF + tid] = s;
        }

        // ---- GEMM1 ----
        float D1[4][4];
        #pragma unroll
        for (int kt = 0; kt < 4; kt++)
            #pragma unroll
            for (int r = 0; r < 4; r++) D1[kt][r] = 0.f;
        #pragma unroll 4
        for (int ds = 0; ds < 16; ds++) {
            const int d0 = ds*8;
            unsigned a0 = fbits(sm[XS_OFF + rowA*ST     + d0 + lc]);
            unsigned a1 = fbits(sm[XS_OFF + (rowA+8)*ST + d0 + lc]);
            unsigned a2 = fbits(sm[XS_OFF + rowA*ST     + d0 + lc + 4]);
            unsigned a3 = fbits(sm[XS_OFF + (rowA+8)*ST + d0 + lc + 4]);
            #pragma unroll
            for (int kt = 0; kt < 4; kt++) {
                unsigned b0 = fbits(sm[CS_OFF + (8*kt+lr)*ST + d0 + lc]);
                unsigned b1 = fbits(sm[CS_OFF + (8*kt+lr)*ST + d0 + lc + 4]);
                mma_tf32(D1[kt], a0, a1, a2, a3, b0, b1);
            }
        }
        __syncthreads();   // X2S visible before softmax reads

        // ---- softmax + As store + warp-level asum partials ----
        {
            const float x2_0 = sm[X2S_OFF + rowA];
            const float x2_1 = sm[X2S_OFF + rowA + 8];
            float sl[4][4];
            #pragma unroll
            for (int kt = 0; kt < 4; kt++) {
                sl[kt][0] = scv[kt][0]*(x2_0 - 2.f*D1[kt][0] + c2v[kt][0]);
                sl[kt][1] = scv[kt][1]*(x2_0 - 2.f*D1[kt][1] + c2v[kt][1]);
                sl[kt][2] = scv[kt][0]*(x2_1 - 2.f*D1[kt][2] + c2v[kt][0]);
                sl[kt][3] = scv[kt][1]*(x2_1 - 2.f*D1[kt][3] + c2v[kt][1]);
            }
            float m0 = -3.4e38f, m1 = -3.4e38f;
            #pragma unroll
            for (int kt = 0; kt < 4; kt++) {
                m0 = fmaxf(m0, fmaxf(sl[kt][0], sl[kt][1]));
                m1 = fmaxf(m1, fmaxf(sl[kt][2], sl[kt][3]));
            }
            m0 = fmaxf(m0, __shfl_xor_sync(~0u, m0, 1));
            m0 = fmaxf(m0, __shfl_xor_sync(~0u, m0, 2));
            m1 = fmaxf(m1, __shfl_xor_sync(~0u, m1, 1));
            m1 = fmaxf(m1, __shfl_xor_sync(~0u, m1, 2));
            float s0 = 0.f, s1 = 0.f;
            #pragma unroll
            for (int kt = 0; kt < 4; kt++) {
                sl[kt][0] = __expf(sl[kt][0] - m0); s0 += sl[kt][0];
                sl[kt][1] = __expf(sl[kt][1] - m0); s0 += sl[kt][1];
                sl[kt][2] = __expf(sl[kt][2] - m1); s1 += sl[kt][2];
                sl[kt][3] = __expf(sl[kt][3] - m1); s1 += sl[kt][3];
            }
            s0 += __shfl_xor_sync(~0u, s0, 1); s0 += __shfl_xor_sync(~0u, s0, 2);
            s1 += __shfl_xor_sync(~0u, s1, 1); s1 += __shfl_xor_sync(~0u, s1, 2);
            const float i0 = 1.f/s0, i1 = 1.f/s1;
            float aw[4][2];
            #pragma unroll
            for (int kt = 0; kt < 4; kt++)
                #pragma unroll
                for (int j = 0; j < 2; j++) {
                    int k = 8*kt + 2*lc + j;
                    float af0 = __uint_as_float(f2tf(sl[kt][j]*i0));
                    float af1 = __uint_as_float(f2tf(sl[kt][2+j]*i1));
                    sm[AS_OFF + k*ST + rowA]     = af0;
                    sm[AS_OFF + k*ST + rowA + 8] = af1;
                    aw[kt][j] = af0 + af1;
                }
            #pragma unroll
            for (int kt = 0; kt < 4; kt++)
                #pragma unroll
                for (int j = 0; j < 2; j++) {
                    float v = aw[kt][j];
                    v += __shfl_xor_sync(~0u, v, 4);
                    v += __shfl_xor_sync(~0u, v, 8);
                    v += __shfl_xor_sync(~0u, v, 16);
                    aw[kt][j] = v;
                }
            if (lr == 0) {
                #pragma unroll
                for (int kt = 0; kt < 4; kt++)
                    #pragma unroll
                    for (int j = 0; j < 2; j++)
                        sm[RED_OFF + w*32 + 8*kt + 2*lc + j] = aw[kt][j];
            }
        }
        __syncthreads();   // As + RED complete

        if (tid < Kk) {
            float s = 0.f;
            #pragma unroll
            for (int ww = 0; ww < 8; ww++) s += sm[RED_OFF + ww*32 + tid];
            asum_acc += s;
        }

        // ---- GEMM2 ----
        #pragma unroll 4
        for (int ns = 0; ns < 16; ns++) {
            const int n0 = ns*8;
            unsigned bx0[2], bx1[2];
            #pragma unroll
            for (int nt = 0; nt < 2; nt++) {
                bx0[nt] = fbits(sm[XS_OFF + (n0+lc)*ST   + dwarp + 8*nt + lr]);
                bx1[nt] = fbits(sm[XS_OFF + (n0+lc+4)*ST + dwarp + 8*nt + lr]);
            }
            #pragma unroll
            for (int mt = 0; mt < 2; mt++) {
                unsigned a0 = fbits(sm[AS_OFF + (16*mt+lr)*ST   + n0 + lc]);
                unsigned a1 = fbits(sm[AS_OFF + (16*mt+lr+8)*ST + n0 + lc]);
                unsigned a2 = fbits(sm[AS_OFF + (16*mt+lr)*ST   + n0 + lc + 4]);
                unsigned a3 = fbits(sm[AS_OFF + (16*mt+lr+8)*ST + n0 + lc + 4]);
                #pragma unroll
                for (int nt = 0; nt < 2; nt++)
                    mma_tf32(D2[mt][nt], a0, a1, a2, a3, bx0[nt], bx1[nt]);
            }
        }
    }

    // ---- epilogue: (E_part - asum*C) -> scratch ----
    if (tid < Kk) sm[ASUM_OFF + tid] = asum_acc;
    __syncthreads();
    {
        float* eo = g_scratchE + (size_t)(b*CH + chunk)*(Kk*Dd);
        #pragma unroll
        for (int mt = 0; mt < 2; mt++) {
            const int k0 = 16*mt + lr;
            const float as0 = sm[ASUM_OFF + k0];
            const float as1 = sm[ASUM_OFF + k0 + 8];
            #pragma unroll
            for (int nt = 0; nt < 2; nt++) {
                const int dc = dwarp + 8*nt + 2*lc;
                float c00 = sm[CS_OFF + k0*ST + dc],     c01 = sm[CS_OFF + k0*ST + dc + 1];
                float c10 = sm[CS_OFF + (k0+8)*ST + dc], c11 = sm[CS_OFF + (k0+8)*ST + dc + 1];
                *(float2*)&eo[k0*Dd + dc] =
                    make_float2(D2[mt][nt][0] - as0*c00, D2[mt][nt][1] - as0*c01);
                *(float2*)&eo[(k0+8)*Dd + dc] =
                    make_float2(D2[mt][nt][2] - as1*c10, D2[mt][nt][3] - as1*c11);
            }
        }
    }

    // ---- fused cross-chunk reduction: per-batch spin barrier, then all 16
    //      CTAs of batch b reduce disjoint 64-float4 output slices ----
    __threadfence();                               // release scratch writes
    if (tid == 0) {
        atomicAdd(&g_cnt[b], 1);
        while (*(volatile int*)&g_cnt[b] < CH) __nanosleep(64);
    }
    __syncthreads();                               // broadcast barrier pass
    __threadfence();                               // acquire scratch reads
    {
        const int sub = tid & 63;                  // float4 within slice
        const int q   = tid >> 6;                  // chunk quarter 0..3
        const int i4  = chunk*64 + sub;            // output float4 (0..1023)
        const float4* src = (const float4*)g_scratchE
                          + ((size_t)b*CH + q*4)*1024 + i4;
        float4 v0 = src[0*1024], v1 = src[1*1024], v2 = src[2*1024], v3 = src[3*1024];
        float4 s;
        s.x = (v0.x + v1.x) + (v2.x + v3.x);
        s.y = (v0.y + v1.y) + (v2.y + v3.y);
        s.z = (v0.z + v1.z) + (v2.z + v3.z);
        s.w = (v0.w + v1.w) + (v2.w + v3.w);
        float4* red4 = (float4*)&sm[XS_OFF];       // reuse Xs area
        red4[tid] = s;
        __syncthreads();
        if (q == 0) {
            float4 a = red4[tid], bb = red4[tid+64], c = red4[tid+128], d = red4[tid+192];
            float4 r;
            r.x = (a.x + bb.x) + (c.x + d.x);
            r.y = (a.y + bb.y) + (c.y + d.y);
            r.z = (a.z + bb.z) + (c.z + d.z);
            r.w = (a.w + bb.w) + (c.w + d.w);
            ((float4*)(out + (size_t)b*(Kk*Dd)))[i4] = r;
        }
    }
    __syncthreads();
    if (tid == 0) {                                // last finisher resets counters
        int old2 = atomicAdd(&g_cnt2[b], 1);
        if (old2 == CH - 1) {
            atomicExch(&g_cnt[b], 0);
            atomicExch(&g_cnt2[b], 0);
        }
    }
}

extern "C" void kernel_launch(void* const* d_in, const int* in_sizes, int n_in,
                              void* d_out, int out_size)
{
    const float* x  = (const float*)d_in[0];
    const float* cw = (const float*)d_in[1];
    const float* sc = (const float*)d_in[2];
    float* out = (float*)d_out;

    cudaFuncSetAttribute(enc_main, cudaFuncAttributeMaxDynamicSharedMemorySize, SM_BYTES);
    enc_main<<<dim3(CH, Bb), NTH, SM_BYTES>>>(x, cw, sc, out);
}

// round 11
// speedup vs baseline: 1.4815x; 1.4815x over previous
#include <cuda_runtime.h>

// Encoding layer on tensor cores (tf32 mma.sync), B=16, D=128, N=4096, K=32.
// One CTA = one (b, chunk) tile of 256 n (two inner 128-n tiles); GEMM2
// accumulators and asum persist across inner tiles. asum*C folded into the
// per-chunk epilogue; reduce kernel: 1 load/thread, fixed-order smem tree.

#define Dd   128
#define Kk   32
#define Bb   16
#define HWn  4096
#define TN   256
#define TIN  128
#define NT   2
#define CH   16          // 4096 / TN
#define NTH  256
#define ST   132

#define XS_OFF   0                    // [128][ST]
#define CS_OFF   (128*ST)             // [32][ST]
#define AS_OFF   (160*ST)             // [32][ST]
#define X2P_OFF  (192*ST)             // [8][128]
#define X2S_OFF  (X2P_OFF + 1024)     // [128]
#define C2S_OFF  (X2S_OFF + 128)      // [32]
#define RED_OFF  (C2S_OFF + 32)       // [256]
#define ASUM_OFF (RED_OFF + 256)      // [32]
#define SM_FLOATS (ASUM_OFF + 32)
#define SM_BYTES  (SM_FLOATS * 4)

__device__ float g_scratchE[Bb*CH*Kk*Dd];   // 4 MB partial E (asum*C folded)

__device__ __forceinline__ unsigned f2tf(float f) {
    unsigned r; asm("cvt.rna.tf32.f32 %0, %1;" : "=r"(r) : "f"(f)); return r;
}
__device__ __forceinline__ void mma_tf32(float* d,
    unsigned a0, unsigned a1, unsigned a2, unsigned a3, unsigned b0, unsigned b1) {
    asm("mma.sync.aligned.m16n8k8.row.col.f32.tf32.tf32.f32 "
        "{%0,%1,%2,%3}, {%4,%5,%6,%7}, {%8,%9}, {%0,%1,%2,%3};"
        : "+f"(d[0]), "+f"(d[1]), "+f"(d[2]), "+f"(d[3])
        : "r"(a0), "r"(a1), "r"(a2), "r"(a3), "r"(b0), "r"(b1));
}
__device__ __forceinline__ unsigned fbits(float f) { return __float_as_uint(f); }

__global__ void __launch_bounds__(NTH, 2) enc_main(
    const float* __restrict__ x,      // (B, D, HWn)
    const float* __restrict__ cw,     // (K, D)
    const float* __restrict__ scale)  // (K,)
{
    extern __shared__ float sm[];
    const int tid = threadIdx.x;
    const int w   = tid >> 5;
    const int l   = tid & 31;
    const int lr  = l >> 2;
    const int lc  = l & 3;
    const int b     = blockIdx.y;
    const int chunk = blockIdx.x;
    const float* xb = x + (size_t)b * Dd * HWn + chunk * TN;

    // ---- stage Cs (tf32-rounded) once per CTA ----
    #pragma unroll 1
    for (int i = tid; i < Kk*Dd; i += NTH)
        sm[CS_OFF + (i >> 7)*ST + (i & 127)] = __uint_as_float(f2tf(cw[i]));
    __syncthreads();
    {
        int k = tid >> 3, s8 = tid & 7;
        float part = 0.f;
        #pragma unroll
        for (int j = 0; j < 16; j++) {
            float c = sm[CS_OFF + k*ST + s8*16 + j];
            part += c*c;
        }
        sm[RED_OFF + tid] = part;
    }
    __syncthreads();
    if (tid < Kk) {
        float s = 0.f;
        #pragma unroll
        for (int j = 0; j < 8; j++) s += sm[RED_OFF + tid*8 + j];
        sm[C2S_OFF + tid] = s;
    }
    __syncthreads();

    float c2v[4][2], scv[4][2];
    #pragma unroll
    for (int kt = 0; kt < 4; kt++)
        #pragma unroll
        for (int j = 0; j < 2; j++) {
            int k = 8*kt + 2*lc + j;
            c2v[kt][j] = sm[C2S_OFF + k];
            scv[kt][j] = scale[k];
        }

    const int rowA  = 16*w + lr;
    const int dwarp = 16*w;

    float D2[2][2][4];
    #pragma unroll
    for (int mt = 0; mt < 2; mt++)
        #pragma unroll
        for (int nt = 0; nt < 2; nt++)
            #pragma unroll
            for (int r = 0; r < 4; r++) D2[mt][nt][r] = 0.f;
    float asum_acc = 0.f;            // valid in tid<32

    for (int t = 0; t < NT; t++) {
        __syncthreads();

        // ---- fill Xs (tf32) + exact-fp32 x2 partials ----
        {
            const int nl = tid & 31, dq = tid >> 5;
            #pragma unroll
            for (int p = 0; p < 4; p++) {
                const int n = p*32 + nl;
                const float* src = xb + (size_t)(dq*16)*HWn + t*TIN + n;
                float* dst = &sm[XS_OFF + n*ST + dq*16];
                float part = 0.f;
                #pragma unroll
                for (int j = 0; j < 4; j++) {
                    float v0 = src[(size_t)(4*j+0)*HWn];
                    float v1 = src[(size_t)(4*j+1)*HWn];
                    float v2 = src[(size_t)(4*j+2)*HWn];
                    float v3 = src[(size_t)(4*j+3)*HWn];
                    part += v0*v0 + v1*v1 + v2*v2 + v3*v3;
                    float4 o;
                    o.x = __uint_as_float(f2tf(v0)); o.y = __uint_as_float(f2tf(v1));
                    o.z = __uint_as_float(f2tf(v2)); o.w = __uint_as_float(f2tf(v3));
                    *(float4*)(dst + 4*j) = o;
                }
                sm[X2P_OFF + dq*128 + n] = part;
            }
        }
        __syncthreads();

        if (tid < 128) {
            float s = 0.f;
            #pragma unroll
            for (int dq = 0; dq < 8; dq++) s += sm[X2P_OFF + dq*128 + tid];
            sm[X2S_OFF + tid] = s;
        }

        // ---- GEMM1: xc[n,k] ----
        float D1[4][4];
        #pragma unroll
        for (int kt = 0; kt < 4; kt++)
            #pragma unroll
            for (int r = 0; r < 4; r++) D1[kt][r] = 0.f;
        #pragma unroll 4
        for (int ds = 0; ds < 16; ds++) {
            const int d0 = ds*8;
            unsigned a0 = fbits(sm[XS_OFF + rowA*ST     + d0 + lc]);
            unsigned a1 = fbits(sm[XS_OFF + (rowA+8)*ST + d0 + lc]);
            unsigned a2 = fbits(sm[XS_OFF + rowA*ST     + d0 + lc + 4]);
            unsigned a3 = fbits(sm[XS_OFF + (rowA+8)*ST + d0 + lc + 4]);
            #pragma unroll
            for (int kt = 0; kt < 4; kt++) {
                unsigned b0 = fbits(sm[CS_OFF + (8*kt+lr)*ST + d0 + lc]);
                unsigned b1 = fbits(sm[CS_OFF + (8*kt+lr)*ST + d0 + lc + 4]);
                mma_tf32(D1[kt], a0, a1, a2, a3, b0, b1);
            }
        }
        __syncthreads();   // X2S visible to all before softmax reads

        // ---- softmax over K=32 ----
        {
            const float x2_0 = sm[X2S_OFF + rowA];
            const float x2_1 = sm[X2S_OFF + rowA + 8];
            float sl[4][4];
            #pragma unroll
            for (int kt = 0; kt < 4; kt++) {
                sl[kt][0] = scv[kt][0]*(x2_0 - 2.f*D1[kt][0] + c2v[kt][0]);
                sl[kt][1] = scv[kt][1]*(x2_0 - 2.f*D1[kt][1] + c2v[kt][1]);
                sl[kt][2] = scv[kt][0]*(x2_1 - 2.f*D1[kt][2] + c2v[kt][0]);
                sl[kt][3] = scv[kt][1]*(x2_1 - 2.f*D1[kt][3] + c2v[kt][1]);
            }
            float m0 = -3.4e38f, m1 = -3.4e38f;
            #pragma unroll
            for (int kt = 0; kt < 4; kt++) {
                m0 = fmaxf(m0, fmaxf(sl[kt][0], sl[kt][1]));
                m1 = fmaxf(m1, fmaxf(sl[kt][2], sl[kt][3]));
            }
            m0 = fmaxf(m0, __shfl_xor_sync(~0u, m0, 1));
            m0 = fmaxf(m0, __shfl_xor_sync(~0u, m0, 2));
            m1 = fmaxf(m1, __shfl_xor_sync(~0u, m1, 1));
            m1 = fmaxf(m1, __shfl_xor_sync(~0u, m1, 2));
            float s0 = 0.f, s1 = 0.f;
            #pragma unroll
            for (int kt = 0; kt < 4; kt++) {
                sl[kt][0] = __expf(sl[kt][0] - m0); s0 += sl[kt][0];
                sl[kt][1] = __expf(sl[kt][1] - m0); s0 += sl[kt][1];
                sl[kt][2] = __expf(sl[kt][2] - m1); s1 += sl[kt][2];
                sl[kt][3] = __expf(sl[kt][3] - m1); s1 += sl[kt][3];
            }
            s0 += __shfl_xor_sync(~0u, s0, 1); s0 += __shfl_xor_sync(~0u, s0, 2);
            s1 += __shfl_xor_sync(~0u, s1, 1); s1 += __shfl_xor_sync(~0u, s1, 2);
            const float i0 = 1.f/s0, i1 = 1.f/s1;
            #pragma unroll
            for (int kt = 0; kt < 4; kt++)
                #pragma unroll
                for (int j = 0; j < 2; j++) {
                    int k = 8*kt + 2*lc + j;
                    sm[AS_OFF + k*ST + rowA]     = __uint_as_float(f2tf(sl[kt][j]*i0));
                    sm[AS_OFF + k*ST + rowA + 8] = __uint_as_float(f2tf(sl[kt][2+j]*i1));
                }
        }
        __syncthreads();   // As complete

        // ---- asum partials from the SAME rounded A ----
        {
            int k = tid >> 3, ns = tid & 7;
            float s = 0.f;
            #pragma unroll
            for (int i = 0; i < 16; i++) s += sm[AS_OFF + k*ST + ns + 8*i];
            sm[RED_OFF + tid] = s;
        }
        __syncthreads();
        if (tid < Kk) {
            float s = 0.f;
            #pragma unroll
            for (int j = 0; j < 8; j++) s += sm[RED_OFF + tid*8 + j];
            asum_acc += s;
        }

        // ---- GEMM2: accumulate E[k,d] over this tile's n ----
        #pragma unroll 4
        for (int ns = 0; ns < 16; ns++) {
            const int n0 = ns*8;
            unsigned bx0[2], bx1[2];
            #pragma unroll
            for (int nt = 0; nt < 2; nt++) {
                bx0[nt] = fbits(sm[XS_OFF + (n0+lc)*ST   + dwarp + 8*nt + lr]);
                bx1[nt] = fbits(sm[XS_OFF + (n0+lc+4)*ST + dwarp + 8*nt + lr]);
            }
            #pragma unroll
            for (int mt = 0; mt < 2; mt++) {
                unsigned a0 = fbits(sm[AS_OFF + (16*mt+lr)*ST   + n0 + lc]);
                unsigned a1 = fbits(sm[AS_OFF + (16*mt+lr+8)*ST + n0 + lc]);
                unsigned a2 = fbits(sm[AS_OFF + (16*mt+lr)*ST   + n0 + lc + 4]);
                unsigned a3 = fbits(sm[AS_OFF + (16*mt+lr+8)*ST + n0 + lc + 4]);
                #pragma unroll
                for (int nt = 0; nt < 2; nt++)
                    mma_tf32(D2[mt][nt], a0, a1, a2, a3, bx0[nt], bx1[nt]);
            }
        }
    }

    // ---- ASUM publish + epilogue ----
    if (tid < Kk) sm[ASUM_OFF + tid] = asum_acc;
    __syncthreads();
    {
        float* eo = g_scratchE + (size_t)(b*CH + chunk)*(Kk*Dd);
        #pragma unroll
        for (int mt = 0; mt < 2; mt++) {
            const int k0 = 16*mt + lr;
            const float as0 = sm[ASUM_OFF + k0];
            const float as1 = sm[ASUM_OFF + k0 + 8];
            #pragma unroll
            for (int nt = 0; nt < 2; nt++) {
                const int dc = dwarp + 8*nt + 2*lc;
                float c00 = sm[CS_OFF + k0*ST + dc],     c01 = sm[CS_OFF + k0*ST + dc + 1];
                float c10 = sm[CS_OFF + (k0+8)*ST + dc], c11 = sm[CS_OFF + (k0+8)*ST + dc + 1];
                *(float2*)&eo[k0*Dd + dc] =
                    make_float2(D2[mt][nt][0] - as0*c00, D2[mt][nt][1] - as0*c01);
                *(float2*)&eo[(k0+8)*Dd + dc] =
                    make_float2(D2[mt][nt][2] - as1*c10, D2[mt][nt][3] - as1*c11);
            }
        }
    }
}

// reduce: block handles 16 output float4s; thread (o, c) loads chunk c's
// partial for output o (ONE gmem load per thread), fixed-order smem tree.
__global__ void __launch_bounds__(256) enc_reduce(float* __restrict__ out)
{
    __shared__ float4 red[256];
    const int tid = threadIdx.x;
    const int o   = tid & 15;                    // output within block
    const int c   = tid >> 4;                    // chunk 0..15
    const int i4  = blockIdx.x*16 + o;           // global output float4 (0..16383)
    const int b   = i4 >> 10;                    // 1024 float4 per batch plane
    const int j   = i4 & 1023;
    red[tid] = ((const float4*)g_scratchE)[((size_t)b*CH + c)*1024 + j];
    __syncthreads();
    if (tid < 64) {                              // fold chunks {c, c+4, c+8, c+12}
        float4 a = red[tid], bb = red[tid+64], cc = red[tid+128], d = red[tid+192];
        float4 s;
        s.x = (a.x + bb.x) + (cc.x + d.x);
        s.y = (a.y + bb.y) + (cc.y + d.y);
        s.z = (a.z + bb.z) + (cc.z + d.z);
        s.w = (a.w + bb.w) + (cc.w + d.w);
        red[tid] = s;
    }
    __syncthreads();
    if (tid < 16) {
        float4 a = red[tid], bb = red[tid+16], cc = red[tid+32], d = red[tid+48];
        float4 r;
        r.x = (a.x + bb.x) + (cc.x + d.x);
        r.y = (a.y + bb.y) + (cc.y + d.y);
        r.z = (a.z + bb.z) + (cc.z + d.z);
        r.w = (a.w + bb.w) + (cc.w + d.w);
        ((float4*)out)[i4] = r;
    }
}

extern "C" void kernel_launch(void* const* d_in, const int* in_sizes, int n_in,
                              void* d_out, int out_size)
{
    const float* x  = (const float*)d_in[0];
    const float* cw = (const float*)d_in[1];
    const float* sc = (const float*)d_in[2];
    float* out = (float*)d_out;

    cudaFuncSetAttribute(enc_main, cudaFuncAttributeMaxDynamicSharedMemorySize, SM_BYTES);
    enc_main<<<dim3(CH, Bb), NTH, SM_BYTES>>>(x, cw, sc);
    enc_reduce<<<1024, 256>>>(out);
}